// round 17
// baseline (speedup 1.0000x reference)
#include <cuda_runtime.h>
#include <math.h>

// Problem constants (fixed by the reference: B=8, N=8192, D=3)
#define BATCH   8
#define NPTS    8192
#define TOTAL   (BATCH * NPTS)        // 65536
#define BG      16                    // Morton bin cells per axis
#define BNC     (BG * BG * BG)        // 4096 bins per batch
#define GRID_LO (-4.5f)
#define BIN_H   (0.5625f)             // 9.0 / 16
#define BIN_INV (1.0f / BIN_H)
#define F_INF   __int_as_float(0x7f800000)
#define TPTS    128                   // ori points per tile
#define NTILE   (NPTS / TPTS)         // 64 tiles per batch
#define QTHREADS 128
#define QPERBLK  256                  // queries per block (2 per thread)
#define QBLOCKS  (TOTAL / QPERBLK)    // 256

// Static scratch (no device allocation allowed).
__device__ int    g_off_ori[BATCH * BNC];   // batch-local ori bin offsets (for home lookup)
__device__ float4 g_sorted_ori[TOTAL];      // (x, y, z, 0.5*||o||^2), Morton order
__device__ float4 g_sorted_adv[TOTAL];      // (x, y, z, ||a||^2),    Morton order
__device__ int    g_adv_meta[TOTAL];        // (bin << 13) | orig-index-in-batch
__device__ float4 g_tlo[BATCH * NTILE];     // tile AABB lows
__device__ float4 g_thi[BATCH * NTILE];     // tile AABB highs
__device__ float  g_res[TOTAL];             // per-query nearest dist^2, original order

__device__ __forceinline__ int bin1(float v) {
    int c = (int)floorf((v - GRID_LO) * BIN_INV);
    return min(BG - 1, max(0, c));
}
__device__ __forceinline__ unsigned spread3(unsigned x) {
    x &= 0x3FF;
    x = (x | (x << 16)) & 0x030000FF;
    x = (x | (x << 8))  & 0x0300F00F;
    x = (x | (x << 4))  & 0x030C30C3;
    x = (x | (x << 2))  & 0x09249249;
    return x;
}
__device__ __forceinline__ int morton3(int cx, int cy, int cz) {
    return (int)(spread3(cx) | (spread3(cy) << 1) | (spread3(cz) << 2));
}

// ---------------------------------------------------------------- bin (fused zero+count+scan+scatter[+aabb])
// 16 blocks x 1024 threads: block b<8 handles ori batch b, block b>=8 adv batch b-8.
// All binning state lives in smem; one kernel replaces four.
__global__ __launch_bounds__(1024) void k_bin(const float* __restrict__ ori,
                                              const float* __restrict__ adv) {
    __shared__ int s_cur[BNC];     // histogram, then running cursors (16 KB)
    __shared__ int s_off[BNC];     // scanned offsets (16 KB)
    __shared__ int s_scan[1024];   // block scan scratch (4 KB)

    const int blk = blockIdx.x;
    const bool is_ori = blk < 8;
    const int b = blk & 7;
    const int t = threadIdx.x;
    const float* __restrict__ src = (is_ori ? ori : adv) + (size_t)b * NPTS * 3;

    // zero histogram
#pragma unroll
    for (int j = 0; j < BNC / 1024; j++) s_cur[t + j * 1024] = 0;
    __syncthreads();

    // count (cache bin ids; 8 points per thread)
    int pb[8];
#pragma unroll
    for (int k = 0; k < 8; k++) {
        const int i = k * 1024 + t;
        const float x = src[i * 3], y = src[i * 3 + 1], z = src[i * 3 + 2];
        pb[k] = morton3(bin1(x), bin1(y), bin1(z));
        atomicAdd(&s_cur[pb[k]], 1);
    }
    __syncthreads();

    // exclusive scan over 4096 bins (4 per thread + Hillis-Steele over 1024)
    const int base = t * 4;
    const int l0 = s_cur[base], l1 = s_cur[base + 1], l2 = s_cur[base + 2], l3 = s_cur[base + 3];
    const int tot = l0 + l1 + l2 + l3;
    s_scan[t] = tot;
    __syncthreads();
    for (int d = 1; d < 1024; d <<= 1) {
        int v = (t >= d) ? s_scan[t - d] : 0;
        __syncthreads();
        s_scan[t] += v;
        __syncthreads();
    }
    int run = s_scan[t] - tot;
    s_off[base] = run;     s_cur[base] = run;     run += l0;
    s_off[base + 1] = run; s_cur[base + 1] = run; run += l1;
    s_off[base + 2] = run; s_cur[base + 2] = run; run += l2;
    s_off[base + 3] = run; s_cur[base + 3] = run;
    if (is_ori) {   // publish ori offsets for the query home-tile lookup
#pragma unroll
        for (int j = 0; j < 4; j++) g_off_ori[b * BNC + base + j] = s_off[base + j];
    }
    __syncthreads();

    // scatter (re-read coords; L2-hot)
#pragma unroll
    for (int k = 0; k < 8; k++) {
        const int i = k * 1024 + t;
        const float x = src[i * 3], y = src[i * 3 + 1], z = src[i * 3 + 2];
        const int pos = atomicAdd(&s_cur[pb[k]], 1);
        if (is_ori) {
            g_sorted_ori[b * NPTS + pos] = make_float4(x, y, z, 0.5f * (x * x + y * y + z * z));
        } else {
            g_sorted_adv[b * NPTS + pos] = make_float4(x, y, z, x * x + y * y + z * z);
            g_adv_meta[b * NPTS + pos] = (pb[k] << 13) | i;
        }
    }

    if (is_ori) {
        __syncthreads();   // block-scope fence: sorted ori visible to this block
        // tile AABBs: 32 warps, each does tiles wid and wid+32
        const int wid = t >> 5, lane = t & 31;
        for (int tt = wid; tt < NTILE; tt += 32) {
            float lx = F_INF, ly = F_INF, lz = F_INF;
            float hx = -F_INF, hy = -F_INF, hz = -F_INF;
#pragma unroll
            for (int k = 0; k < 4; k++) {
                float4 p = g_sorted_ori[b * NPTS + tt * TPTS + k * 32 + lane];
                lx = fminf(lx, p.x); ly = fminf(ly, p.y); lz = fminf(lz, p.z);
                hx = fmaxf(hx, p.x); hy = fmaxf(hy, p.y); hz = fmaxf(hz, p.z);
            }
#pragma unroll
            for (int s = 16; s > 0; s >>= 1) {
                lx = fminf(lx, __shfl_xor_sync(0xffffffffu, lx, s));
                ly = fminf(ly, __shfl_xor_sync(0xffffffffu, ly, s));
                lz = fminf(lz, __shfl_xor_sync(0xffffffffu, lz, s));
                hx = fmaxf(hx, __shfl_xor_sync(0xffffffffu, hx, s));
                hy = fmaxf(hy, __shfl_xor_sync(0xffffffffu, hy, s));
                hz = fmaxf(hz, __shfl_xor_sync(0xffffffffu, hz, s));
            }
            if (lane == 0) {
                g_tlo[b * NTILE + tt] = make_float4(lx, ly, lz, 0.f);
                g_thi[b * NTILE + tt] = make_float4(hx, hy, hz, 0.f);
            }
        }
    }
}

// ---------------------------------------------------------------- query
// R13 skeleton + one-time per-warp tile need-masks (built against seed-time
// best; conservative & exact since mn only decreases). Chunks with no block
// need are skipped entirely; only needed subtiles are staged/evaluated.
__global__ __launch_bounds__(QTHREADS) void k_query() {
    __shared__ __align__(16) float4 s_tile[1024];        // 16 KB
    __shared__ float4 s_lo[NTILE], s_hi[NTILE];          // 2 KB
    __shared__ unsigned s_wm[8];                         // 4 warps x {lo,hi}

    const int tid = threadIdx.x;
    const int wid = tid >> 5, lane = tid & 31;
    const int b = blockIdx.x >> 5;                       // 32 blocks per batch
    const int qbase = (blockIdx.x & 31) * QPERBLK;
    const float4* __restrict__ so = g_sorted_ori + b * NPTS;
    const float4* __restrict__ sa = g_sorted_adv + b * NPTS;

    if (tid < NTILE) { s_lo[tid] = g_tlo[b * NTILE + tid]; s_hi[tid] = g_thi[b * NTILE + tid]; }

    // My two adjacent sorted queries: warp w owns [qbase+64w, +64).
    const int q0 = qbase + wid * 64 + lane * 2;
    const float4 qa = sa[q0], qb = sa[q0 + 1];
    const int meta0 = g_adv_meta[b * NPTS + q0];
    const int meta1 = g_adv_meta[b * NPTS + q0 + 1];
    const float nax = -qa.x, nay = -qa.y, naz = -qa.z, ra0 = qa.w;
    const float nbx = -qb.x, nby = -qb.y, nbz = -qb.z, ra1 = qb.w;
    float mn0 = F_INF, mn1 = F_INF;

    // Seed: evaluate the warp's (median lane's) home tile via uniform LDG.
    int ht = min(g_off_ori[b * BNC + (meta0 >> 13)] >> 7, NTILE - 1);
    ht = __shfl_sync(0xffffffffu, ht, 16);
    {
        const float4* __restrict__ tp = so + ht * TPTS;
#pragma unroll 4
        for (int j = 0; j < TPTS; j++) {
            const float4 o = __ldg(tp + j);
            mn0 = fminf(mn0, fmaf(nax, o.x, fmaf(nay, o.y, fmaf(naz, o.z, o.w))));
            mn1 = fminf(mn1, fmaf(nbx, o.x, fmaf(nby, o.y, fmaf(nbz, o.z, o.w))));
        }
    }
    __syncthreads();   // AABBs staged

    // One-time need-mask: tile needed iff ANY lane's bound beats seed-time best.
    unsigned mlo = 0, mhi = 0;
    {
        const float bA = fmaf(2.0f, mn0, ra0), bB = fmaf(2.0f, mn1, ra1);
        for (int t = 0; t < NTILE; t++) {
            const float4 lo = s_lo[t], hi = s_hi[t];
            float dx = fmaxf(fmaxf(lo.x - qa.x, qa.x - hi.x), 0.0f);
            float dy = fmaxf(fmaxf(lo.y - qa.y, qa.y - hi.y), 0.0f);
            float dz = fmaxf(fmaxf(lo.z - qa.z, qa.z - hi.z), 0.0f);
            const float bdA = fmaf(dx, dx, fmaf(dy, dy, dz * dz));
            dx = fmaxf(fmaxf(lo.x - qb.x, qb.x - hi.x), 0.0f);
            dy = fmaxf(fmaxf(lo.y - qb.y, qb.y - hi.y), 0.0f);
            dz = fmaxf(fmaxf(lo.z - qb.z, qb.z - hi.z), 0.0f);
            const float bdB = fmaf(dx, dx, fmaf(dy, dy, dz * dz));
            const bool need = (bdA < bA) || (bdB < bB);
            const unsigned bal = __ballot_sync(0xffffffffu, need);
            if (bal) { if (t < 32) mlo |= 1u << t; else mhi |= 1u << (t - 32); }
        }
        // home tile already evaluated at seed
        if (ht < 32) mlo &= ~(1u << ht); else mhi &= ~(1u << (ht - 32));
    }
    if (lane == 0) { s_wm[wid * 2] = mlo; s_wm[wid * 2 + 1] = mhi; }
    __syncthreads();
    const unsigned blo = s_wm[0] | s_wm[2] | s_wm[4] | s_wm[6];
    const unsigned bhi = s_wm[1] | s_wm[3] | s_wm[5] | s_wm[7];

    // Chunk loop: stage only block-needed subtiles, eval only warp-needed.
    for (int c = 0; c < 8; c++) {
        const unsigned bbyte = ((c < 4) ? (blo >> (8 * c)) : (bhi >> (8 * (c - 4)))) & 0xFFu;
        if (!bbyte) continue;
        const int t0 = c * 1024;
#pragma unroll
        for (int sub = 0; sub < 8; sub++)
            if ((bbyte >> sub) & 1)
                s_tile[sub * TPTS + tid] = __ldg(so + t0 + sub * TPTS + tid);
        __syncthreads();
        const unsigned wbyte = ((c < 4) ? (mlo >> (8 * c)) : (mhi >> (8 * (c - 4)))) & 0xFFu;
        for (int sub = 0; sub < 8; sub++) {
            if (!((wbyte >> sub) & 1)) continue;
            const float4* __restrict__ sp = s_tile + sub * TPTS;
#pragma unroll 8
            for (int j = 0; j < TPTS; j++) {
                const float4 o = sp[j];   // broadcast LDS.128
                mn0 = fminf(mn0, fmaf(nax, o.x, fmaf(nay, o.y, fmaf(naz, o.z, o.w))));
                mn1 = fminf(mn1, fmaf(nbx, o.x, fmaf(nby, o.y, fmaf(nbz, o.z, o.w))));
            }
        }
        __syncthreads();
    }

    g_res[b * NPTS + (meta0 & (NPTS - 1))] = fmaf(2.0f, mn0, ra0);
    g_res[b * NPTS + (meta1 & (NPTS - 1))] = fmaf(2.0f, mn1, ra1);
}

// ---------------------------------------------------------------- reduce
// One block, fixed strided assignment + fixed tree: bit-deterministic.
__global__ void k_reduce(const float* __restrict__ weights, float* __restrict__ out) {
    __shared__ float s[1024];
    int t = threadIdx.x;
    float sum = 0.0f;
    for (int i = t; i < TOTAL; i += 1024)
        sum += g_res[i] * __ldg(&weights[i >> 13]);
    s[t] = sum;
    __syncthreads();
    for (int d = 512; d > 0; d >>= 1) {
        if (t < d) s[t] += s[t + d];
        __syncthreads();
    }
    if (t == 0) out[0] = s[0] * (1.0f / (float)TOTAL);
}

extern "C" void kernel_launch(void* const* d_in, const int* in_sizes, int n_in,
                              void* d_out, int out_size) {
    const float* adv     = (const float*)d_in[0];  // adv_pc  [B, N, 3]  (queries)
    const float* ori     = (const float*)d_in[1];  // ori_pc  [B, N, 3]  (targets)
    const float* weights = (const float*)d_in[2];  // weights [B]
    float* out = (float*)d_out;                    // scalar

    k_bin   <<<16, 1024>>>(ori, adv);
    k_query <<<QBLOCKS, QTHREADS>>>();
    k_reduce<<<1, 1024>>>(weights, out);
}